// round 7
// baseline (speedup 1.0000x reference)
#include <cuda_runtime.h>
#include <cuda_bf16.h>
#include <cstdint>

#define Bsz 2048
#define Tt  100
#define Uu  512
#define Cc  10
#define G4  2048   // 4*U

#define BM      64       // compacted batch rows per CTA job
#define THREADS 256      // 8 warps = 2 rowWarps x 4 colWarps
#define NS      2        // pipeline stages

#define A_BYTES 8192     // 64 rows x 128B (64 bf16 k)
#define B_BYTES 32768    // 256 cols x 128B
#define STAGE_BYTES (A_BYTES + B_BYTES)     // 40960
#define SMEM_TOTAL (NS * STAGE_BYTES + 1024)

#define NDIAG (Tt + 2)
#define NJOBS 768        // 3 layers x 8 nt x 32 row-tiles

// ---------------- device state ----------------
__device__ __nv_bfloat16 g_h[3][2][Bsz * Uu];                 // ping-pong h, PLAIN [b][512]
__device__ float         g_c[3][Bsz * Uu];                     // c fp32, linear
__device__ __align__(1024) __nv_bfloat16 g_w0[512  * G4];      // tiled+swizzled bf16 weights
__device__ __align__(1024) __nv_bfloat16 g_w1[1024 * G4];
__device__ __align__(1024) __nv_bfloat16 g_w2[1024 * G4];
__device__ int g_order[Tt][Bsz];                               // per-t: active rows, then inactive
__device__ int g_count[Tt];
__device__ unsigned g_ticket[NDIAG];
__device__ unsigned g_barcnt;
__device__ volatile unsigned g_epoch;

// ---------------- helpers ----------------
__device__ __forceinline__ void mbar_init(uint32_t a, uint32_t cnt) {
    asm volatile("mbarrier.init.shared::cta.b64 [%0], %1;" ::"r"(a), "r"(cnt) : "memory");
}
__device__ __forceinline__ void mbar_expect_tx(uint32_t a, uint32_t bytes) {
    asm volatile("mbarrier.arrive.expect_tx.shared::cta.b64 _, [%0], %1;" ::"r"(a), "r"(bytes) : "memory");
}
__device__ __forceinline__ void mbar_wait(uint32_t a, uint32_t parity) {
    asm volatile(
        "{\n\t"
        ".reg .pred P;\n\t"
        "WL%=:\n\t"
        "mbarrier.try_wait.parity.acquire.cta.shared::cta.b64 P, [%0], %1, 0x989680;\n\t"
        "@P bra WD%=;\n\t"
        "bra WL%=;\n\t"
        "WD%=:\n\t"
        "}" ::"r"(a), "r"(parity) : "memory");
}
__device__ __forceinline__ void bulk_g2s(uint32_t dst, const void* src, uint32_t bytes, uint32_t mbar) {
    asm volatile(
        "cp.async.bulk.shared::cluster.global.mbarrier::complete_tx::bytes [%0], [%1], %2, [%3];"
        ::"r"(dst), "l"(src), "r"(bytes), "r"(mbar) : "memory");
}
__device__ __forceinline__ void cp16(uint32_t dst, const void* src) {
    asm volatile("cp.async.cg.shared.global [%0], [%1], 16;" ::"r"(dst), "l"(src));
}
__device__ __forceinline__ void mma_bf16(float* d, const unsigned* a, const unsigned* b) {
    asm volatile(
        "mma.sync.aligned.m16n8k16.row.col.f32.bf16.bf16.f32 "
        "{%0,%1,%2,%3}, {%4,%5,%6,%7}, {%8,%9}, {%0,%1,%2,%3};"
        : "+f"(d[0]), "+f"(d[1]), "+f"(d[2]), "+f"(d[3])
        : "r"(a[0]), "r"(a[1]), "r"(a[2]), "r"(a[3]), "r"(b[0]), "r"(b[1]));
}
// L2-coherent (bypass L1) accessors — required inside the persistent kernel,
// where L1 is NOT flushed between diagonals and h/c cross SMs.
__device__ __forceinline__ unsigned ldcg_u32(const void* p) {
    unsigned v; asm volatile("ld.global.cg.b32 %0, [%1];" : "=r"(v) : "l"(p)); return v;
}
__device__ __forceinline__ void stcg_u32(void* p, unsigned v) {
    asm volatile("st.global.cg.b32 [%0], %1;" ::"l"(p), "r"(v));
}
__device__ __forceinline__ float2 ldcg_f2(const void* p) {
    float2 v; asm volatile("ld.global.cg.v2.f32 {%0,%1}, [%2];" : "=f"(v.x), "=f"(v.y) : "l"(p)); return v;
}
__device__ __forceinline__ void stcg_f2(void* p, float2 v) {
    asm volatile("st.global.cg.v2.f32 [%0], {%1,%2};" ::"l"(p), "f"(v.x), "f"(v.y));
}
__device__ __forceinline__ uint4 ldcg_v4(const void* p) {
    uint4 v;
    asm volatile("ld.global.cg.v4.b32 {%0,%1,%2,%3}, [%4];"
                 : "=r"(v.x), "=r"(v.y), "=r"(v.z), "=r"(v.w) : "l"(p));
    return v;
}
__device__ __forceinline__ void stcg_v4(void* p, uint4 v) {
    asm volatile("st.global.cg.v4.b32 [%0], {%1,%2,%3,%4};"
                 ::"l"(p), "r"(v.x), "r"(v.y), "r"(v.z), "r"(v.w));
}
__device__ __forceinline__ float fsigmoid(float x) { return 1.0f / (1.0f + __expf(-x)); }
__device__ __forceinline__ float ftanh(float x)    { return 1.0f - 2.0f / (__expf(2.0f * x) + 1.0f); }

// ---------------- prep kernels ----------------
__global__ void zero_state_kernel() {
    int nh = 3 * 2 * Bsz * Uu;
    int nc = 3 * Bsz * Uu;
    __nv_bfloat16* h = &g_h[0][0][0];
    float* c = &g_c[0][0];
    for (int i = blockIdx.x * blockDim.x + threadIdx.x; i < nh; i += gridDim.x * blockDim.x)
        h[i] = __float2bfloat16(0.0f);
    for (int i = blockIdx.x * blockDim.x + threadIdx.x; i < nc; i += gridDim.x * blockDim.x)
        c[i] = 0.0f;
    if (blockIdx.x == 0 && threadIdx.x == 0) {
        g_barcnt = 0;
        *(unsigned*)&g_epoch = 0;
    }
    if (blockIdx.x == 1 && threadIdx.x < NDIAG) g_ticket[threadIdx.x] = 0;
}

// Stable partition of batch rows by mask for each timestep.
__global__ void compact_kernel(const int* __restrict__ mask) {
    __shared__ int part[256];
    int t   = blockIdx.x;
    int tid = threadIdx.x;
    int ml[8], lc = 0;
#pragma unroll
    for (int j = 0; j < 8; j++) {
        int b = tid * 8 + j;
        ml[j] = (mask[b * Tt + t] != 0) ? 1 : 0;
        lc += ml[j];
    }
    part[tid] = lc;
    __syncthreads();
    for (int off = 1; off < 256; off <<= 1) {
        int v = (tid >= off) ? part[tid - off] : 0;
        __syncthreads();
        part[tid] += v;
        __syncthreads();
    }
    int incl  = part[tid];
    int base  = incl - lc;
    int total = part[255];
    int a = base, iv = tid * 8 - base;
#pragma unroll
    for (int j = 0; j < 8; j++) {
        int b = tid * 8 + j;
        if (ml[j]) g_order[t][a++]          = b;
        else       g_order[t][total + iv++] = b;
    }
    if (tid == 0) g_count[t] = total;
}

// Build tiled + SW128-preswizzled bf16 weight blocks. Block (nt,kt): 256 cols x 64 k.
__global__ void wprep_kernel(const float* __restrict__ W, const float* __restrict__ Uw, int layer) {
    int K   = (layer == 0) ? 512 : 1024;
    int Klo = (layer == 0) ? 0 : 512;
    int nkt = K / 64;
    char* dst = (char*)((layer == 0) ? g_w0 : ((layer == 1) ? g_w1 : g_w2));
    int totalPairs = K * G4 / 2;
    for (int idx = blockIdx.x * blockDim.x + threadIdx.x; idx < totalPairs;
         idx += gridDim.x * blockDim.x) {
        int klp = idx & 31;
        int c   = (idx >> 5) & 255;
        int blk = idx >> 13;
        int kt  = blk % nkt;
        int nt  = blk / nkt;
        int z   = (c >> 6) * 512 + nt * 64 + (c & 63);
        int kg  = kt * 64 + klp * 2;
        float v0, v1;
        if (kg < Klo) { v0 = W[kg * G4 + z]; v1 = W[(kg + 1) * G4 + z]; }
        else          { v0 = Uw[(kg - Klo) * G4 + z]; v1 = Uw[(kg + 1 - Klo) * G4 + z]; }
        uint32_t off = (uint32_t)(nt * nkt + kt) * B_BYTES + c * 128 +
                       (((uint32_t)klp * 4) ^ (((uint32_t)c & 7) * 16));
        *(__nv_bfloat162*)(dst + off) = __floats2bfloat162_rn(v0, v1);
    }
}

// ---------------- persistent wavefront LSTM ----------------
__global__ void __launch_bounds__(THREADS, 2)
lstm_persist_kernel(const float* __restrict__ x, const int* __restrict__ mask,
                    const float* __restrict__ b0, const float* __restrict__ b1,
                    const float* __restrict__ b2, const float* __restrict__ W0,
                    int nCTA)
{
    extern __shared__ char smem[];
    __shared__ __align__(16) uint64_t barmem[NS];
    __shared__ int ords[BM];
    __shared__ int js;

    const uint32_t sdata = ((uint32_t)__cvta_generic_to_shared(smem) + 1023u) & ~1023u;
    const uint32_t barb  = (uint32_t)__cvta_generic_to_shared(barmem);

    const int tid  = threadIdx.x;
    const int lane = tid & 31, warp = tid >> 5;
    const int colWarp = warp & 3, rowWarp = warp >> 2;
    const int g = lane >> 2, tig = lane & 3;
    const uint32_t msk = (uint32_t)g * 16;

    if (tid == 0) {
        for (int s = 0; s < NS; s++) mbar_init(barb + 8 * s, 1);
        asm volatile("fence.proxy.async.shared::cta;" ::: "memory");
    }
    __syncthreads();

    unsigned epoch = 0;

    for (int d = 0; d < NDIAG; d++) {
        for (;;) {
            __syncthreads();
            if (tid == 0) js = (int)atomicAdd(&g_ticket[d], 1u);
            __syncthreads();
            int j = js;
            if (j >= NJOBS) break;

            // decode: big K=1024 layers (1,2) first, then layer 0
            int lsel  = j >> 8;
            int layer = (lsel == 0) ? 1 : ((lsel == 1) ? 2 : 0);
            int t     = d - layer;
            if (t < 0 || t >= Tt) continue;
            int r     = j & 255;
            int nt    = r >> 5;
            int row0  = (r & 31) * BM;
            int count = g_count[t];
            if (row0 >= count && nt != 0) continue;

            const int nkt = (layer == 0) ? 8 : 16;
            const char* wB = (const char*)((layer == 0) ? g_w0 : ((layer == 1) ? g_w1 : g_w2));
            const float* bias = (layer == 0) ? b0 : ((layer == 1) ? b1 : b2);
            const int p = t & 1;
            const char* hOwnOld = (const char*)g_h[layer][p];
            char*       hOwnNew = (char*)g_h[layer][p ^ 1];
            const char* hLow    = (layer == 0) ? hOwnOld : (const char*)g_h[layer - 1][p ^ 1];
            float*      Cst     = g_c[layer];
            const int u0 = nt * 64;

            if (tid < BM) ords[tid] = g_order[t][row0 + tid];
            __syncthreads();

            if (row0 >= count) {
                // copy job (nt==0): h_new = h_old for inactive rows
                for (int idx = tid; idx < BM * 64; idx += THREADS) {
                    int rr = idx >> 6, ck = idx & 63;
                    size_t off = (size_t)ords[rr] * 1024 + ck * 16;
                    stcg_v4(hOwnNew + off, ldcg_v4(hOwnOld + off));
                }
                continue;
            }

            // ---- producers ----
            auto issueA = [&](int kt, int s) {
                const char* base = (kt < 8) ? (hLow + (size_t)kt * 128)
                                            : (hOwnOld + (size_t)(kt - 8) * 128);
#pragma unroll
                for (int i = 0; i < 2; i++) {
                    int c  = i * THREADS + tid;
                    int rr = c >> 3, ck = c & 7;
                    uint32_t dst = sdata + s * STAGE_BYTES + rr * 128 +
                                   (((uint32_t)ck * 16) ^ (((uint32_t)rr & 7) * 16));
                    cp16(dst, base + (size_t)ords[rr] * 1024 + ck * 16);
                }
                asm volatile("cp.async.commit_group;");
            };
            auto issueB = [&](int kt, int s) {
                uint32_t full = barb + 8 * s;
                mbar_expect_tx(full, B_BYTES);
                bulk_g2s(sdata + s * STAGE_BYTES + A_BYTES,
                         wB + (size_t)(nt * nkt + kt) * B_BYTES, B_BYTES, full);
            };

            issueA(0, 0);
            if (tid == 0) issueB(0, 0);
            issueA(1, 1);
            if (tid == 0) issueB(1, 1);

            float acc[2][8][4];
#pragma unroll
            for (int m = 0; m < 2; m++)
#pragma unroll
                for (int jj = 0; jj < 8; jj++)
#pragma unroll
                    for (int rr = 0; rr < 4; rr++) acc[m][jj][rr] = 0.0f;

            for (int kt = 0; kt < nkt; kt++) {
                int s = kt & 1;
                if (kt + 1 == nkt) asm volatile("cp.async.wait_group 0;");
                else               asm volatile("cp.async.wait_group 1;");
                mbar_wait(barb + 8 * s, (uint32_t)((kt >> 1) & 1));
                __syncthreads();

                const char* As = smem + (sdata - (uint32_t)__cvta_generic_to_shared(smem)) +
                                 s * STAGE_BYTES;
                const char* Bs = As + A_BYTES;

#pragma unroll
                for (int kq = 0; kq < 4; kq++) {
                    const uint32_t kb0 = (uint32_t)kq * 32 + (uint32_t)tig * 4;
                    unsigned af[2][4];
#pragma unroll
                    for (int m = 0; m < 2; m++) {
                        int rb = rowWarp * 32 + m * 16 + g;
                        const char* r0p = As + rb * 128;
                        const char* r8p = r0p + 8 * 128;
                        af[m][0] = *(const unsigned*)(r0p + (kb0 ^ msk));
                        af[m][1] = *(const unsigned*)(r8p + (kb0 ^ msk));
                        af[m][2] = *(const unsigned*)(r0p + ((kb0 + 16) ^ msk));
                        af[m][3] = *(const unsigned*)(r8p + ((kb0 + 16) ^ msk));
                    }
                    unsigned bfm[8][2];
#pragma unroll
                    for (int jj = 0; jj < 8; jj++) {
                        int cb = (jj >> 1) * 64 + colWarp * 16 + (jj & 1) * 8 + g;
                        const char* cp = Bs + cb * 128;
                        bfm[jj][0] = *(const unsigned*)(cp + (kb0 ^ msk));
                        bfm[jj][1] = *(const unsigned*)(cp + ((kb0 + 16) ^ msk));
                    }
#pragma unroll
                    for (int m = 0; m < 2; m++)
#pragma unroll
                        for (int jj = 0; jj < 8; jj++)
                            mma_bf16(acc[m][jj], af[m], bfm[jj]);
                }
                __syncthreads();

                if (kt + NS < nkt) {
                    issueA(kt + NS, s);
                    if (tid == 0) issueB(kt + NS, s);
                }
            }

            // ---- fused epilogue ----
#pragma unroll
            for (int m = 0; m < 2; m++) {
#pragma unroll
                for (int rs = 0; rs < 2; rs++) {
                    int ro = rowWarp * 32 + m * 16 + g + rs * 8;
                    int bg = ords[ro];
                    int mk = mask[bg * Tt + t];
                    float xv = (layer == 0) ? x[bg * Tt + t] : 0.0f;
#pragma unroll
                    for (int half = 0; half < 2; half++) {
                        int u = u0 + colWarp * 16 + half * 8 + tig * 2;   // even
                        size_t hoff = (size_t)bg * 1024 + (size_t)u * 2;
                        unsigned hraw = ldcg_u32(hOwnOld + hoff);
                        __nv_bfloat162 hold2 = *(__nv_bfloat162*)&hraw;
                        float2 c2 = ldcg_f2(&Cst[bg * Uu + u]);
                        float cv[2] = {c2.x, c2.y}, hv[2];
#pragma unroll
                        for (int pp = 0; pp < 2; pp++) {
                            int uu = u + pp;
                            int ri = rs * 2 + pp;
                            float zi = acc[m][0 + half][ri] + bias[uu];
                            float zf = acc[m][2 + half][ri] + bias[512 + uu];
                            float zg = acc[m][4 + half][ri] + bias[1024 + uu];
                            float zo = acc[m][6 + half][ri] + bias[1536 + uu];
                            if (layer == 0) {
                                zi += xv * W0[uu];
                                zf += xv * W0[512 + uu];
                                zg += xv * W0[1024 + uu];
                                zo += xv * W0[1536 + uu];
                            }
                            float co = cv[pp];
                            float ig = fsigmoid(zi);
                            float fg = fsigmoid(zf);
                            float gg = ftanh(zg);
                            float og = fsigmoid(zo);
                            float cn = fg * co + ig * gg;
                            float hn = og * ftanh(cn);
                            if (!mk) { cn = co; hn = __bfloat162float(pp ? hold2.y : hold2.x); }
                            cv[pp] = cn;
                            hv[pp] = hn;
                        }
                        stcg_f2(&Cst[bg * Uu + u], make_float2(cv[0], cv[1]));
                        __nv_bfloat162 hq = __floats2bfloat162_rn(hv[0], hv[1]);
                        stcg_u32(hOwnNew + hoff, *(unsigned*)&hq);
                    }
                }
            }
        }

        // ---- global diagonal barrier (all nCTA CTAs resident by construction) ----
        epoch++;
        if (tid == 0) {
            __threadfence();
            unsigned old = atomicAdd(&g_barcnt, 1u);
            if (old == (unsigned)nCTA - 1u) {
                atomicExch(&g_barcnt, 0u);
                __threadfence();
                atomicAdd((unsigned*)&g_epoch, 1u);
            } else {
                while (g_epoch < epoch) __nanosleep(64);
            }
        }
        __syncthreads();
        __threadfence();
    }
}

// ---------------- softmax head ----------------
__global__ void head_kernel(const float* __restrict__ Wd, const float* __restrict__ bd,
                            float* __restrict__ out)
{
    int gw   = (blockIdx.x * blockDim.x + threadIdx.x) >> 5;
    int lane = threadIdx.x & 31;
    if (gw >= Bsz) return;
    const __nv_bfloat16* h = g_h[2][0];   // layer2 @ t=99 writes buffer (99&1)^1 = 0
    float a[Cc];
#pragma unroll
    for (int c = 0; c < Cc; c++) a[c] = 0.0f;
    for (int k = lane; k < Uu; k += 32) {
        float hv = __bfloat162float(h[(size_t)gw * Uu + k]);
#pragma unroll
        for (int c = 0; c < Cc; c++) a[c] += hv * Wd[k * Cc + c];
    }
#pragma unroll
    for (int c = 0; c < Cc; c++)
#pragma unroll
        for (int off = 16; off > 0; off >>= 1)
            a[c] += __shfl_xor_sync(0xffffffffu, a[c], off);
    if (lane == 0) {
        float logit[Cc], mx = -1e30f;
#pragma unroll
        for (int c = 0; c < Cc; c++) { logit[c] = a[c] + bd[c]; mx = fmaxf(mx, logit[c]); }
        float s = 0.0f;
#pragma unroll
        for (int c = 0; c < Cc; c++) { logit[c] = expf(logit[c] - mx); s += logit[c]; }
        float inv = 1.0f / s;
#pragma unroll
        for (int c = 0; c < Cc; c++) out[gw * Cc + c] = logit[c] * inv;
    }
}

// ---------------- launch ----------------
extern "C" void kernel_launch(void* const* d_in, const int* in_sizes, int n_in,
                              void* d_out, int out_size)
{
    const float* x    = (const float*)d_in[0];
    const int*   mask = (const int*)  d_in[1];
    const float* W0   = (const float*)d_in[2];
    const float* U0   = (const float*)d_in[3];
    const float* b0   = (const float*)d_in[4];
    const float* W1   = (const float*)d_in[5];
    const float* U1   = (const float*)d_in[6];
    const float* b1   = (const float*)d_in[7];
    const float* W2   = (const float*)d_in[8];
    const float* U2   = (const float*)d_in[9];
    const float* b2   = (const float*)d_in[10];
    const float* Wd   = (const float*)d_in[11];
    const float* bd   = (const float*)d_in[12];
    float* out = (float*)d_out;

    cudaFuncSetAttribute(lstm_persist_kernel, cudaFuncAttributeMaxDynamicSharedMemorySize,
                         SMEM_TOTAL);

    // residency-safe grid size for the device barrier
    int dev = 0;
    cudaGetDevice(&dev);
    int smCount = 0;
    cudaDeviceGetAttribute(&smCount, cudaDevAttrMultiProcessorCount, dev);
    int maxB = 0;
    cudaOccupancyMaxActiveBlocksPerMultiprocessor(&maxB, lstm_persist_kernel, THREADS, SMEM_TOTAL);
    if (maxB < 1) maxB = 1;
    int nCTA = smCount * maxB;
    if (nCTA < 1) nCTA = 1;

    zero_state_kernel<<<256, 256>>>();
    wprep_kernel<<<256, 256>>>((const float*)0, U0, 0);
    wprep_kernel<<<512, 256>>>(W1, U1, 1);
    wprep_kernel<<<512, 256>>>(W2, U2, 2);
    compact_kernel<<<Tt, 256>>>(mask);

    lstm_persist_kernel<<<nCTA, THREADS, SMEM_TOTAL>>>(x, mask, b0, b1, b2, W0, nCTA);

    head_kernel<<<(Bsz * 32 + 255) / 256, 256>>>(Wd, bd, out);
}

// round 11
// speedup vs baseline: 1.1012x; 1.1012x over previous
#include <cuda_runtime.h>
#include <cuda_bf16.h>
#include <cstdint>

#define Bsz 2048
#define Tt  100
#define Uu  512
#define Cc  10
#define G4  2048   // 4*U

#define BM      64       // compacted batch rows per CTA
#define THREADS 256      // 8 warps = 2 rowWarps x 4 colWarps
#define NS      4        // pipeline stages

#define A_BYTES 8192     // 64 rows x 128B (64 bf16 k)
#define B_BYTES 16384    // 128 cols x 128B
#define STAGE_BYTES (A_BYTES + B_BYTES)     // 24576
#define SMEM_TOTAL (NS * STAGE_BYTES + 1024)

// ---------------- device state ----------------
__device__ __nv_bfloat16 g_h[3][2][Bsz * Uu];                 // ping-pong h, PLAIN [b][512]
__device__ float         g_c[3][Bsz * Uu];                     // c fp32, linear
__device__ __align__(1024) __nv_bfloat16 g_w0[512  * G4];      // tiled+swizzled bf16 weights
__device__ __align__(1024) __nv_bfloat16 g_w1[1024 * G4];
__device__ __align__(1024) __nv_bfloat16 g_w2[1024 * G4];
__device__ int g_order[Tt][Bsz];                               // per-t: active rows, then inactive
__device__ int g_count[Tt];

// ---------------- helpers ----------------
__device__ __forceinline__ void mbar_init(uint32_t a, uint32_t cnt) {
    asm volatile("mbarrier.init.shared::cta.b64 [%0], %1;" ::"r"(a), "r"(cnt) : "memory");
}
__device__ __forceinline__ void mbar_expect_tx(uint32_t a, uint32_t bytes) {
    asm volatile("mbarrier.arrive.expect_tx.shared::cta.b64 _, [%0], %1;" ::"r"(a), "r"(bytes) : "memory");
}
__device__ __forceinline__ void mbar_wait(uint32_t a, uint32_t parity) {
    asm volatile(
        "{\n\t"
        ".reg .pred P;\n\t"
        "WL%=:\n\t"
        "mbarrier.try_wait.parity.acquire.cta.shared::cta.b64 P, [%0], %1, 0x989680;\n\t"
        "@P bra WD%=;\n\t"
        "bra WL%=;\n\t"
        "WD%=:\n\t"
        "}" ::"r"(a), "r"(parity) : "memory");
}
__device__ __forceinline__ void bulk_g2s(uint32_t dst, const void* src, uint32_t bytes, uint32_t mbar) {
    asm volatile(
        "cp.async.bulk.shared::cluster.global.mbarrier::complete_tx::bytes [%0], [%1], %2, [%3];"
        ::"r"(dst), "l"(src), "r"(bytes), "r"(mbar) : "memory");
}
__device__ __forceinline__ void cp16(uint32_t dst, const void* src) {
    asm volatile("cp.async.cg.shared.global [%0], [%1], 16;" ::"r"(dst), "l"(src));
}
__device__ __forceinline__ void mma_bf16(float* d, const unsigned* a, const unsigned* b) {
    asm volatile(
        "mma.sync.aligned.m16n8k16.row.col.f32.bf16.bf16.f32 "
        "{%0,%1,%2,%3}, {%4,%5,%6,%7}, {%8,%9}, {%0,%1,%2,%3};"
        : "+f"(d[0]), "+f"(d[1]), "+f"(d[2]), "+f"(d[3])
        : "r"(a[0]), "r"(a[1]), "r"(a[2]), "r"(a[3]), "r"(b[0]), "r"(b[1]));
}
__device__ __forceinline__ float fsigmoid(float x) { return 1.0f / (1.0f + __expf(-x)); }
__device__ __forceinline__ float ftanh(float x)    { return 1.0f - 2.0f / (__expf(2.0f * x) + 1.0f); }

// ---------------- prep kernels ----------------
__global__ void zero_state_kernel() {
    int nh = 3 * 2 * Bsz * Uu;
    int nc = 3 * Bsz * Uu;
    __nv_bfloat16* h = &g_h[0][0][0];
    float* c = &g_c[0][0];
    for (int i = blockIdx.x * blockDim.x + threadIdx.x; i < nh; i += gridDim.x * blockDim.x)
        h[i] = __float2bfloat16(0.0f);
    for (int i = blockIdx.x * blockDim.x + threadIdx.x; i < nc; i += gridDim.x * blockDim.x)
        c[i] = 0.0f;
}

// Stable partition of batch rows by mask for each timestep.
__global__ void compact_kernel(const int* __restrict__ mask) {
    __shared__ int part[256];
    int t   = blockIdx.x;
    int tid = threadIdx.x;
    int ml[8], lc = 0;
#pragma unroll
    for (int j = 0; j < 8; j++) {
        int b = tid * 8 + j;
        ml[j] = (mask[b * Tt + t] != 0) ? 1 : 0;
        lc += ml[j];
    }
    part[tid] = lc;
    __syncthreads();
    for (int off = 1; off < 256; off <<= 1) {
        int v = (tid >= off) ? part[tid - off] : 0;
        __syncthreads();
        part[tid] += v;
        __syncthreads();
    }
    int incl  = part[tid];
    int base  = incl - lc;
    int total = part[255];
    int a = base, iv = tid * 8 - base;
#pragma unroll
    for (int j = 0; j < 8; j++) {
        int b = tid * 8 + j;
        if (ml[j]) g_order[t][a++]          = b;
        else       g_order[t][total + iv++] = b;
    }
    if (tid == 0) g_count[t] = total;
}

// Build tiled + SW128-preswizzled bf16 weight blocks.
// Block (nt,kt): 128 cols x 64 k, [col][k] layout, 16KB each. nt in [0,16).
// col c of tile -> z = (c>>5)*512 + nt*32 + (c&31)   (gate-major interleave)
__global__ void wprep_kernel(const float* __restrict__ W, const float* __restrict__ Uw, int layer) {
    int K   = (layer == 0) ? 512 : 1024;
    int Klo = (layer == 0) ? 0 : 512;
    int nkt = K / 64;
    char* dst = (char*)((layer == 0) ? g_w0 : ((layer == 1) ? g_w1 : g_w2));
    int totalPairs = K * G4 / 2;
    for (int idx = blockIdx.x * blockDim.x + threadIdx.x; idx < totalPairs;
         idx += gridDim.x * blockDim.x) {
        int klp = idx & 31;           // k-pair within 64
        int c   = (idx >> 5) & 127;   // col within tile
        int blk = idx >> 12;
        int kt  = blk % nkt;
        int nt  = blk / nkt;
        int z   = (c >> 5) * 512 + nt * 32 + (c & 31);
        int kg  = kt * 64 + klp * 2;
        float v0, v1;
        if (kg < Klo) { v0 = W[kg * G4 + z]; v1 = W[(kg + 1) * G4 + z]; }
        else          { v0 = Uw[(kg - Klo) * G4 + z]; v1 = Uw[(kg + 1 - Klo) * G4 + z]; }
        uint32_t off = (uint32_t)(nt * nkt + kt) * B_BYTES + c * 128 +
                       (((uint32_t)klp * 4) ^ (((uint32_t)c & 7) * 16));
        *(__nv_bfloat162*)(dst + off) = __floats2bfloat162_rn(v0, v1);
    }
}

// ---------------- fused LSTM diagonal step ----------------
// Diagonal d: layer = blockIdx.z processes t = d - layer (wavefront).
__global__ void __launch_bounds__(THREADS, 2)
lstm_diag_kernel(const float* __restrict__ x, const int* __restrict__ mask,
                 const float* __restrict__ b0, const float* __restrict__ b1,
                 const float* __restrict__ b2, const float* __restrict__ W0,
                 int d)
{
    const int layer = blockIdx.z;
    const int t = d - layer;
    if (t < 0 || t >= Tt) return;

    const int nkt = (layer == 0) ? 8 : 16;
    const char* wB = (const char*)((layer == 0) ? g_w0 : ((layer == 1) ? g_w1 : g_w2));
    const float* bias = (layer == 0) ? b0 : ((layer == 1) ? b1 : b2);
    const int p = t & 1;
    const char* hOwnOld = (const char*)g_h[layer][p];
    char*       hOwnNew = (char*)g_h[layer][p ^ 1];
    const char* hLow    = (layer == 0) ? hOwnOld : (const char*)g_h[layer - 1][p ^ 1];
    float*      Cst     = g_c[layer];

    extern __shared__ char smem[];
    __shared__ __align__(16) uint64_t barmem[NS];
    __shared__ int ords[BM];

    const uint32_t sdata = ((uint32_t)__cvta_generic_to_shared(smem) + 1023u) & ~1023u;
    const uint32_t barb  = (uint32_t)__cvta_generic_to_shared(barmem);

    const int tid  = threadIdx.x;
    const int lane = tid & 31, warp = tid >> 5;
    const int colWarp = warp & 3, rowWarp = warp >> 2;
    const int g = lane >> 2, tig = lane & 3;
    const int nt   = blockIdx.x;          // 0..15
    const int row0 = blockIdx.y * BM;
    const int u0   = nt * 32;
    const int count = g_count[t];

    if (row0 >= count && nt != 0) return;

    if (tid < BM) ords[tid] = g_order[t][row0 + tid];
    if (tid == 0) {
        for (int s = 0; s < NS; s++) mbar_init(barb + 8 * s, 1);
        asm volatile("fence.proxy.async.shared::cta;" ::: "memory");
    }
    __syncthreads();

    if (row0 >= count) {
        // pure copy CTA (nt==0): h_new = h_old for these inactive rows
        for (int idx = tid; idx < BM * 64; idx += THREADS) {
            int r  = idx >> 6, ck = idx & 63;
            size_t off = (size_t)ords[r] * 1024 + ck * 16;
            *(uint4*)(hOwnNew + off) = *(const uint4*)(hOwnOld + off);
        }
        return;
    }

    // ---- producers ----
    auto issueA = [&](int kt, int s) {
        const char* base = (kt < 8) ? (hLow + (size_t)kt * 128)
                                    : (hOwnOld + (size_t)(kt - 8) * 128);
#pragma unroll
        for (int i = 0; i < 2; i++) {
            int c  = i * THREADS + tid;
            int r  = c >> 3, ck = c & 7;
            uint32_t dst = sdata + s * STAGE_BYTES + r * 128 +
                           (((uint32_t)ck * 16) ^ (((uint32_t)r & 7) * 16));
            cp16(dst, base + (size_t)ords[r] * 1024 + ck * 16);
        }
        asm volatile("cp.async.commit_group;");
    };
    auto issueB = [&](int kt, int s) {
        uint32_t full = barb + 8 * s;
        mbar_expect_tx(full, B_BYTES);
        bulk_g2s(sdata + s * STAGE_BYTES + A_BYTES,
                 wB + (size_t)(nt * nkt + kt) * B_BYTES, B_BYTES, full);
    };

#pragma unroll
    for (int s = 0; s < NS; s++) {
        issueA(s, s);
        if (tid == 0) issueB(s, s);
    }

    float acc[2][4][4];
#pragma unroll
    for (int m = 0; m < 2; m++)
#pragma unroll
        for (int j = 0; j < 4; j++)
#pragma unroll
            for (int r = 0; r < 4; r++) acc[m][j][r] = 0.0f;

    const uint32_t msk = (uint32_t)g * 16;

    for (int kt = 0; kt < nkt; kt++) {
        int s = kt & (NS - 1);
        // A-group wait: allow min(NS-1, nkt-1-kt) pending groups
        int rem = nkt - 1 - kt;
        if (rem >= 3)      asm volatile("cp.async.wait_group 3;");
        else if (rem == 2) asm volatile("cp.async.wait_group 2;");
        else if (rem == 1) asm volatile("cp.async.wait_group 1;");
        else               asm volatile("cp.async.wait_group 0;");
        mbar_wait(barb + 8 * s, (uint32_t)((kt >> 2) & 1));
        __syncthreads();

        const char* As = smem + (sdata - (uint32_t)__cvta_generic_to_shared(smem)) + s * STAGE_BYTES;
        const char* Bs = As + A_BYTES;

#pragma unroll
        for (int kq = 0; kq < 4; kq++) {
            const uint32_t kb0 = (uint32_t)kq * 32 + (uint32_t)tig * 4;
            unsigned af[2][4];
#pragma unroll
            for (int m = 0; m < 2; m++) {
                int rb = rowWarp * 32 + m * 16 + g;
                const char* r0p = As + rb * 128;
                const char* r8p = r0p + 8 * 128;
                af[m][0] = *(const unsigned*)(r0p + (kb0 ^ msk));
                af[m][1] = *(const unsigned*)(r8p + (kb0 ^ msk));
                af[m][2] = *(const unsigned*)(r0p + ((kb0 + 16) ^ msk));
                af[m][3] = *(const unsigned*)(r8p + ((kb0 + 16) ^ msk));
            }
            unsigned bf[4][2];
#pragma unroll
            for (int j = 0; j < 4; j++) {
                int cb = j * 32 + colWarp * 8 + g;     // gate j, unit block colWarp
                const char* cp = Bs + cb * 128;
                bf[j][0] = *(const unsigned*)(cp + (kb0 ^ msk));
                bf[j][1] = *(const unsigned*)(cp + ((kb0 + 16) ^ msk));
            }
#pragma unroll
            for (int m = 0; m < 2; m++)
#pragma unroll
                for (int j = 0; j < 4; j++)
                    mma_bf16(acc[m][j], af[m], bf[j]);
        }
        __syncthreads();

        if (kt + NS < nkt) {
            issueA(kt + NS, s);
            if (tid == 0) issueB(kt + NS, s);
        }
    }

    // ---- fused epilogue: acc[m][gate][ri]; units u0 + colWarp*8 + tig*2 + pp ----
#pragma unroll
    for (int m = 0; m < 2; m++) {
#pragma unroll
        for (int rs = 0; rs < 2; rs++) {
            int ro = rowWarp * 32 + m * 16 + g + rs * 8;
            int bg = ords[ro];
            int mk = mask[bg * Tt + t];
            float xv = (layer == 0) ? x[bg * Tt + t] : 0.0f;
            int u = u0 + colWarp * 8 + tig * 2;   // even
            size_t hoff = (size_t)bg * 1024 + (size_t)u * 2;
            __nv_bfloat162 hold2 = *(const __nv_bfloat162*)(hOwnOld + hoff);
            float2 c2 = *(const float2*)&Cst[bg * Uu + u];
            float cv[2] = {c2.x, c2.y}, hv[2];
#pragma unroll
            for (int pp = 0; pp < 2; pp++) {
                int uu = u + pp;
                int ri = rs * 2 + pp;
                float zi = acc[m][0][ri] + bias[uu];
                float zf = acc[m][1][ri] + bias[512 + uu];
                float zg = acc[m][2][ri] + bias[1024 + uu];
                float zo = acc[m][3][ri] + bias[1536 + uu];
                if (layer == 0) {
                    zi += xv * W0[uu];
                    zf += xv * W0[512 + uu];
                    zg += xv * W0[1024 + uu];
                    zo += xv * W0[1536 + uu];
                }
                float co = cv[pp];
                float ig = fsigmoid(zi);
                float fg = fsigmoid(zf);
                float gg = ftanh(zg);
                float og = fsigmoid(zo);
                float cn = fg * co + ig * gg;
                float hn = og * ftanh(cn);
                if (!mk) { cn = co; hn = __bfloat162float(pp ? hold2.y : hold2.x); }
                cv[pp] = cn;
                hv[pp] = hn;
            }
            *(float2*)&Cst[bg * Uu + u] = make_float2(cv[0], cv[1]);
            *(__nv_bfloat162*)(hOwnNew + hoff) = __floats2bfloat162_rn(hv[0], hv[1]);
        }
    }
}

// ---------------- softmax head ----------------
__global__ void head_kernel(const float* __restrict__ Wd, const float* __restrict__ bd,
                            float* __restrict__ out)
{
    int gw   = (blockIdx.x * blockDim.x + threadIdx.x) >> 5;
    int lane = threadIdx.x & 31;
    if (gw >= Bsz) return;
    const __nv_bfloat16* h = g_h[2][0];   // layer2 @ t=99 writes buffer (99&1)^1 = 0
    float a[Cc];
#pragma unroll
    for (int c = 0; c < Cc; c++) a[c] = 0.0f;
    for (int k = lane; k < Uu; k += 32) {
        float hv = __bfloat162float(h[(size_t)gw * Uu + k]);
#pragma unroll
        for (int c = 0; c < Cc; c++) a[c] += hv * Wd[k * Cc + c];
    }
#pragma unroll
    for (int c = 0; c < Cc; c++)
#pragma unroll
        for (int off = 16; off > 0; off >>= 1)
            a[c] += __shfl_xor_sync(0xffffffffu, a[c], off);
    if (lane == 0) {
        float logit[Cc], mx = -1e30f;
#pragma unroll
        for (int c = 0; c < Cc; c++) { logit[c] = a[c] + bd[c]; mx = fmaxf(mx, logit[c]); }
        float s = 0.0f;
#pragma unroll
        for (int c = 0; c < Cc; c++) { logit[c] = expf(logit[c] - mx); s += logit[c]; }
        float inv = 1.0f / s;
#pragma unroll
        for (int c = 0; c < Cc; c++) out[gw * Cc + c] = logit[c] * inv;
    }
}

// ---------------- launch ----------------
extern "C" void kernel_launch(void* const* d_in, const int* in_sizes, int n_in,
                              void* d_out, int out_size)
{
    const float* x    = (const float*)d_in[0];
    const int*   mask = (const int*)  d_in[1];
    const float* W0   = (const float*)d_in[2];
    const float* U0   = (const float*)d_in[3];
    const float* b0   = (const float*)d_in[4];
    const float* W1   = (const float*)d_in[5];
    const float* U1   = (const float*)d_in[6];
    const float* b1   = (const float*)d_in[7];
    const float* W2   = (const float*)d_in[8];
    const float* U2   = (const float*)d_in[9];
    const float* b2   = (const float*)d_in[10];
    const float* Wd   = (const float*)d_in[11];
    const float* bd   = (const float*)d_in[12];
    float* out = (float*)d_out;

    cudaFuncSetAttribute(lstm_diag_kernel, cudaFuncAttributeMaxDynamicSharedMemorySize,
                         SMEM_TOTAL);

    zero_state_kernel<<<256, 256>>>();
    wprep_kernel<<<256, 256>>>((const float*)0, U0, 0);
    wprep_kernel<<<512, 256>>>(W1, U1, 1);
    wprep_kernel<<<512, 256>>>(W2, U2, 2);
    compact_kernel<<<Tt, 256>>>(mask);

    dim3 grid(16, 32, 3);   // u-tiles x row-tiles x layers (wavefront diagonal)
    for (int d = 0; d <= Tt + 1; d++) {
        lstm_diag_kernel<<<grid, THREADS, SMEM_TOTAL>>>(x, mask, b0, b1, b2, W0, d);
    }
    head_kernel<<<(Bsz * 32 + 255) / 256, 256>>>(Wd, bd, out);
}

// round 13
// speedup vs baseline: 1.2694x; 1.1528x over previous
#include <cuda_runtime.h>
#include <cuda_bf16.h>
#include <cstdint>

#define Bsz 2048
#define Tt  100
#define Uu  512
#define Cc  10
#define G4  2048   // 4*U

#define BM      64       // compacted batch rows per CTA
#define THREADS 256      // 8 warps = 2 rowWarps x 4 colWarps
#define NS      2        // pipeline stages

#define A_BYTES 8192     // 64 rows x 128B (64 bf16 k)
#define B_BYTES 32768    // 256 cols x 128B
#define STAGE_BYTES (A_BYTES + B_BYTES)     // 40960
#define SMEM_TOTAL (NS * STAGE_BYTES + 1024)

// ---------------- device state ----------------
__device__ __nv_bfloat16 g_h[3][2][Bsz * Uu];                 // ping-pong h, PLAIN [b][512]
__device__ float         g_c[3][Bsz * Uu];                     // c fp32, linear
__device__ __align__(1024) __nv_bfloat16 g_w0[512  * G4];      // tiled+swizzled bf16 weights
__device__ __align__(1024) __nv_bfloat16 g_w1[1024 * G4];
__device__ __align__(1024) __nv_bfloat16 g_w2[1024 * G4];
__device__ int g_order[Tt][Bsz];                               // per-t: active rows, then inactive
__device__ int g_count[Tt];

// ---------------- helpers ----------------
__device__ __forceinline__ void mbar_init(uint32_t a, uint32_t cnt) {
    asm volatile("mbarrier.init.shared::cta.b64 [%0], %1;" ::"r"(a), "r"(cnt) : "memory");
}
__device__ __forceinline__ void mbar_expect_tx(uint32_t a, uint32_t bytes) {
    asm volatile("mbarrier.arrive.expect_tx.shared::cta.b64 _, [%0], %1;" ::"r"(a), "r"(bytes) : "memory");
}
__device__ __forceinline__ void mbar_wait(uint32_t a, uint32_t parity) {
    asm volatile(
        "{\n\t"
        ".reg .pred P;\n\t"
        "WL%=:\n\t"
        "mbarrier.try_wait.parity.acquire.cta.shared::cta.b64 P, [%0], %1, 0x989680;\n\t"
        "@P bra WD%=;\n\t"
        "bra WL%=;\n\t"
        "WD%=:\n\t"
        "}" ::"r"(a), "r"(parity) : "memory");
}
__device__ __forceinline__ void bulk_g2s(uint32_t dst, const void* src, uint32_t bytes, uint32_t mbar) {
    asm volatile(
        "cp.async.bulk.shared::cluster.global.mbarrier::complete_tx::bytes [%0], [%1], %2, [%3];"
        ::"r"(dst), "l"(src), "r"(bytes), "r"(mbar) : "memory");
}
__device__ __forceinline__ void cp16(uint32_t dst, const void* src) {
    asm volatile("cp.async.cg.shared.global [%0], [%1], 16;" ::"r"(dst), "l"(src));
}
__device__ __forceinline__ void mma_bf16(float* d, const unsigned* a, const unsigned* b) {
    asm volatile(
        "mma.sync.aligned.m16n8k16.row.col.f32.bf16.bf16.f32 "
        "{%0,%1,%2,%3}, {%4,%5,%6,%7}, {%8,%9}, {%0,%1,%2,%3};"
        : "+f"(d[0]), "+f"(d[1]), "+f"(d[2]), "+f"(d[3])
        : "r"(a[0]), "r"(a[1]), "r"(a[2]), "r"(a[3]), "r"(b[0]), "r"(b[1]));
}
__device__ __forceinline__ void ldsm_x4(unsigned& r0, unsigned& r1, unsigned& r2, unsigned& r3,
                                        uint32_t addr) {
    asm volatile("ldmatrix.sync.aligned.m8n8.x4.shared.b16 {%0,%1,%2,%3}, [%4];"
                 : "=r"(r0), "=r"(r1), "=r"(r2), "=r"(r3) : "r"(addr));
}
__device__ __forceinline__ float fsigmoid(float x) { return 1.0f / (1.0f + __expf(-x)); }
__device__ __forceinline__ float ftanh(float x)    { return 1.0f - 2.0f / (__expf(2.0f * x) + 1.0f); }

// ---------------- fused prep kernel ----------------
//  [0,256)      zero state
//  [256,512)    wprep layer0
//  [512,1024)   wprep layer1
//  [1024,1536)  wprep layer2
//  [1536,1636)  compact (t = bid-1536)
__device__ __forceinline__ void wprep_body(const float* W, const float* Uw, int layer,
                                           int bid, int nblk, int tid) {
    int K   = (layer == 0) ? 512 : 1024;
    int Klo = (layer == 0) ? 0 : 512;
    int nkt = K / 64;
    char* dst = (char*)((layer == 0) ? g_w0 : ((layer == 1) ? g_w1 : g_w2));
    int totalPairs = K * G4 / 2;
    for (int idx = bid * 256 + tid; idx < totalPairs; idx += nblk * 256) {
        int klp = idx & 31;
        int c   = (idx >> 5) & 255;
        int blk = idx >> 13;
        int kt  = blk % nkt;
        int nt  = blk / nkt;
        int z   = (c >> 6) * 512 + nt * 64 + (c & 63);
        int kg  = kt * 64 + klp * 2;
        float v0, v1;
        if (kg < Klo) { v0 = W[kg * G4 + z]; v1 = W[(kg + 1) * G4 + z]; }
        else          { v0 = Uw[(kg - Klo) * G4 + z]; v1 = Uw[(kg + 1 - Klo) * G4 + z]; }
        uint32_t off = (uint32_t)(nt * nkt + kt) * B_BYTES + c * 128 +
                       (((uint32_t)klp * 4) ^ (((uint32_t)c & 7) * 16));
        *(__nv_bfloat162*)(dst + off) = __floats2bfloat162_rn(v0, v1);
    }
}

__global__ void prep_kernel(const int* __restrict__ mask,
                            const float* __restrict__ W1, const float* __restrict__ U0,
                            const float* __restrict__ U1, const float* __restrict__ W2,
                            const float* __restrict__ U2)
{
    const int bid = blockIdx.x, tid = threadIdx.x;
    if (bid < 256) {
        int nh = 3 * 2 * Bsz * Uu;
        int nc = 3 * Bsz * Uu;
        __nv_bfloat16* h = &g_h[0][0][0];
        float* c = &g_c[0][0];
        for (int i = bid * 256 + tid; i < nh; i += 256 * 256)
            h[i] = __float2bfloat16(0.0f);
        for (int i = bid * 256 + tid; i < nc; i += 256 * 256)
            c[i] = 0.0f;
    } else if (bid < 512) {
        wprep_body((const float*)0, U0, 0, bid - 256, 256, tid);
    } else if (bid < 1024) {
        wprep_body(W1, U1, 1, bid - 512, 512, tid);
    } else if (bid < 1536) {
        wprep_body(W2, U2, 2, bid - 1024, 512, tid);
    } else {
        // compact: stable partition of rows by mask at t
        __shared__ int part[256];
        int t = bid - 1536;
        int ml[8], lc = 0;
#pragma unroll
        for (int j = 0; j < 8; j++) {
            int b = tid * 8 + j;
            ml[j] = (mask[b * Tt + t] != 0) ? 1 : 0;
            lc += ml[j];
        }
        part[tid] = lc;
        __syncthreads();
        for (int off = 1; off < 256; off <<= 1) {
            int v = (tid >= off) ? part[tid - off] : 0;
            __syncthreads();
            part[tid] += v;
            __syncthreads();
        }
        int incl  = part[tid];
        int base  = incl - lc;
        int total = part[255];
        int a = base, iv = tid * 8 - base;
#pragma unroll
        for (int j = 0; j < 8; j++) {
            int b = tid * 8 + j;
            if (ml[j]) g_order[t][a++]          = b;
            else       g_order[t][total + iv++] = b;
        }
        if (tid == 0) g_count[t] = total;
    }
}

// ---------------- fused LSTM diagonal step ----------------
// Diagonal d: layer = blockIdx.z processes t = d - layer (wavefront).
__global__ void __launch_bounds__(THREADS, 2)
lstm_diag_kernel(const float* __restrict__ x, const int* __restrict__ mask,
                 const float* __restrict__ b0, const float* __restrict__ b1,
                 const float* __restrict__ b2, const float* __restrict__ W0,
                 int d)
{
    const int layer = blockIdx.z;
    const int t = d - layer;
    if (t < 0 || t >= Tt) return;

    const int nkt = (layer == 0) ? 8 : 16;
    const char* wB = (const char*)((layer == 0) ? g_w0 : ((layer == 1) ? g_w1 : g_w2));
    const float* bias = (layer == 0) ? b0 : ((layer == 1) ? b1 : b2);
    const int p = t & 1;
    const char* hOwnOld = (const char*)g_h[layer][p];
    char*       hOwnNew = (char*)g_h[layer][p ^ 1];
    const char* hLow    = (layer == 0) ? hOwnOld : (const char*)g_h[layer - 1][p ^ 1];
    float*      Cst     = g_c[layer];

    extern __shared__ char smem[];
    __shared__ __align__(16) uint64_t barmem[NS];
    __shared__ int ords[BM];

    const uint32_t sdata = ((uint32_t)__cvta_generic_to_shared(smem) + 1023u) & ~1023u;
    const uint32_t barb  = (uint32_t)__cvta_generic_to_shared(barmem);

    const int tid  = threadIdx.x;
    const int lane = tid & 31, warp = tid >> 5;
    const int colWarp = warp & 3, rowWarp = warp >> 2;
    const int g = lane >> 2, tig = lane & 3;
    const int nt   = blockIdx.x;
    const int row0 = blockIdx.y * BM;
    const int u0   = nt * 64;
    const int count = g_count[t];

    if (row0 >= count && nt != 0) return;

    if (tid < BM) ords[tid] = g_order[t][row0 + tid];
    if (tid == 0) {
        for (int s = 0; s < NS; s++) mbar_init(barb + 8 * s, 1);
        asm volatile("fence.proxy.async.shared::cta;" ::: "memory");
    }
    __syncthreads();

    if (row0 >= count) {
        // pure copy CTA (nt==0): h_new = h_old for these inactive rows
        for (int idx = tid; idx < BM * 64; idx += THREADS) {
            int r  = idx >> 6, ck = idx & 63;
            size_t off = (size_t)ords[r] * 1024 + ck * 16;
            *(uint4*)(hOwnNew + off) = *(const uint4*)(hOwnOld + off);
        }
        return;
    }

    // ---- producers ----
    auto issueA = [&](int kt, int s) {
        const char* base = (kt < 8) ? (hLow + (size_t)kt * 128)
                                    : (hOwnOld + (size_t)(kt - 8) * 128);
#pragma unroll
        for (int i = 0; i < 2; i++) {
            int c  = i * THREADS + tid;
            int r  = c >> 3, ck = c & 7;
            uint32_t dst = sdata + s * STAGE_BYTES + r * 128 +
                           (((uint32_t)ck * 16) ^ (((uint32_t)r & 7) * 16));
            cp16(dst, base + (size_t)ords[r] * 1024 + ck * 16);
        }
        asm volatile("cp.async.commit_group;");
    };
    auto issueB = [&](int kt, int s) {
        uint32_t full = barb + 8 * s;
        mbar_expect_tx(full, B_BYTES);
        bulk_g2s(sdata + s * STAGE_BYTES + A_BYTES,
                 wB + (size_t)(nt * nkt + kt) * B_BYTES, B_BYTES, full);
    };

    issueA(0, 0);
    if (tid == 0) issueB(0, 0);
    issueA(1, 1);
    if (tid == 0) issueB(1, 1);

    float acc[2][8][4];
#pragma unroll
    for (int m = 0; m < 2; m++)
#pragma unroll
        for (int j = 0; j < 8; j++)
#pragma unroll
            for (int r = 0; r < 4; r++) acc[m][j][r] = 0.0f;

    // ---- per-lane ldmatrix address constants ----
    // fragment-identical to the scalar-LDS version (verified lane mapping)
    const int ri = lane & 7, mi = lane >> 3;
    const uint32_t swzL  = (uint32_t)ri * 16;
    const uint32_t aHalf = (uint32_t)(mi >> 1) * 16;                 // A: k-half select
    const uint32_t aRow0 = (uint32_t)(rowWarp * 32 + (mi & 1) * 8 + ri) * 128;  // A m=0
    const uint32_t bHalf = (uint32_t)(mi & 1) * 16;                  // B: k-half select
    const uint32_t bCol  = (uint32_t)(colWarp * 16 + (mi >> 1) * 8 + ri) * 128 + A_BYTES;

    for (int kt = 0; kt < nkt; kt++) {
        int s = kt & 1;
        if (kt + 1 < nkt) asm volatile("cp.async.wait_group 1;");
        else              asm volatile("cp.async.wait_group 0;");    // last tile: full drain
        mbar_wait(barb + 8 * s, (uint32_t)((kt >> 1) & 1));
        __syncthreads();

        const uint32_t sb = sdata + s * STAGE_BYTES;

#pragma unroll
        for (int kq = 0; kq < 4; kq++) {
            const uint32_t kB = (uint32_t)kq * 32;
            unsigned af[2][4];
            ldsm_x4(af[0][0], af[0][1], af[0][2], af[0][3],
                    sb + aRow0 + ((kB + aHalf) ^ swzL));
            ldsm_x4(af[1][0], af[1][1], af[1][2], af[1][3],
                    sb + aRow0 + 16 * 128 + ((kB + aHalf) ^ swzL));
            unsigned bf[8][2];
#pragma unroll
            for (int q = 0; q < 4; q++) {
                ldsm_x4(bf[2 * q][0], bf[2 * q][1], bf[2 * q + 1][0], bf[2 * q + 1][1],
                        sb + bCol + (uint32_t)q * 64 * 128 + ((kB + bHalf) ^ swzL));
            }
#pragma unroll
            for (int m = 0; m < 2; m++)
#pragma unroll
                for (int j = 0; j < 8; j++)
                    mma_bf16(acc[m][j], af[m], bf[j]);
        }
        __syncthreads();

        if (kt + NS < nkt) {
            issueA(kt + NS, s);
            if (tid == 0) issueB(kt + NS, s);
        }
    }

    // ---- fused epilogue ----
#pragma unroll
    for (int m = 0; m < 2; m++) {
#pragma unroll
        for (int rs = 0; rs < 2; rs++) {
            int ro = rowWarp * 32 + m * 16 + g + rs * 8;
            int bg = ords[ro];
            int mk = mask[bg * Tt + t];
            float xv = (layer == 0) ? x[bg * Tt + t] : 0.0f;
#pragma unroll
            for (int half = 0; half < 2; half++) {
                int u = u0 + colWarp * 16 + half * 8 + tig * 2;   // even
                size_t hoff = (size_t)bg * 1024 + (size_t)u * 2;
                __nv_bfloat162 hold2 = *(const __nv_bfloat162*)(hOwnOld + hoff);
                float2 c2 = *(const float2*)&Cst[bg * Uu + u];
                float cv[2] = {c2.x, c2.y}, hv[2];
#pragma unroll
                for (int pp = 0; pp < 2; pp++) {
                    int uu = u + pp;
                    int ri2 = rs * 2 + pp;
                    float zi = acc[m][0 + half][ri2] + bias[uu];
                    float zf = acc[m][2 + half][ri2] + bias[512 + uu];
                    float zg = acc[m][4 + half][ri2] + bias[1024 + uu];
                    float zo = acc[m][6 + half][ri2] + bias[1536 + uu];
                    if (layer == 0) {
                        zi += xv * W0[uu];
                        zf += xv * W0[512 + uu];
                        zg += xv * W0[1024 + uu];
                        zo += xv * W0[1536 + uu];
                    }
                    float co = cv[pp];
                    float ig = fsigmoid(zi);
                    float fg = fsigmoid(zf);
                    float gg = ftanh(zg);
                    float og = fsigmoid(zo);
                    float cn = fg * co + ig * gg;
                    float hn = og * ftanh(cn);
                    if (!mk) { cn = co; hn = __bfloat162float(pp ? hold2.y : hold2.x); }
                    cv[pp] = cn;
                    hv[pp] = hn;
                }
                *(float2*)&Cst[bg * Uu + u] = make_float2(cv[0], cv[1]);
                *(__nv_bfloat162*)(hOwnNew + hoff) = __floats2bfloat162_rn(hv[0], hv[1]);
            }
        }
    }
}

// ---------------- softmax head ----------------
__global__ void head_kernel(const float* __restrict__ Wd, const float* __restrict__ bd,
                            float* __restrict__ out)
{
    int gw   = (blockIdx.x * blockDim.x + threadIdx.x) >> 5;
    int lane = threadIdx.x & 31;
    if (gw >= Bsz) return;
    const __nv_bfloat16* h = g_h[2][0];   // layer2 @ t=99 writes buffer (99&1)^1 = 0
    float a[Cc];
#pragma unroll
    for (int c = 0; c < Cc; c++) a[c] = 0.0f;
    for (int k = lane; k < Uu; k += 32) {
        float hv = __bfloat162float(h[(size_t)gw * Uu + k]);
#pragma unroll
        for (int c = 0; c < Cc; c++) a[c] += hv * Wd[k * Cc + c];
    }
#pragma unroll
    for (int c = 0; c < Cc; c++)
#pragma unroll
        for (int off = 16; off > 0; off >>= 1)
            a[c] += __shfl_xor_sync(0xffffffffu, a[c], off);
    if (lane == 0) {
        float logit[Cc], mx = -1e30f;
#pragma unroll
        for (int c = 0; c < Cc; c++) { logit[c] = a[c] + bd[c]; mx = fmaxf(mx, logit[c]); }
        float s = 0.0f;
#pragma unroll
        for (int c = 0; c < Cc; c++) { logit[c] = expf(logit[c] - mx); s += logit[c]; }
        float inv = 1.0f / s;
#pragma unroll
        for (int c = 0; c < Cc; c++) out[gw * Cc + c] = logit[c] * inv;
    }
}

// ---------------- launch ----------------
extern "C" void kernel_launch(void* const* d_in, const int* in_sizes, int n_in,
                              void* d_out, int out_size)
{
    const float* x    = (const float*)d_in[0];
    const int*   mask = (const int*)  d_in[1];
    const float* W0   = (const float*)d_in[2];
    const float* U0   = (const float*)d_in[3];
    const float* b0   = (const float*)d_in[4];
    const float* W1   = (const float*)d_in[5];
    const float* U1   = (const float*)d_in[6];
    const float* b1   = (const float*)d_in[7];
    const float* W2   = (const float*)d_in[8];
    const float* U2   = (const float*)d_in[9];
    const float* b2   = (const float*)d_in[10];
    const float* Wd   = (const float*)d_in[11];
    const float* bd   = (const float*)d_in[12];
    float* out = (float*)d_out;

    cudaFuncSetAttribute(lstm_diag_kernel, cudaFuncAttributeMaxDynamicSharedMemorySize,
                         SMEM_TOTAL);

    prep_kernel<<<1636, 256>>>(mask, W1, U0, U1, W2, U2);

    dim3 grid(8, 32, 3);   // u-tiles x row-tiles x layers (wavefront diagonal)
    for (int d = 0; d <= Tt + 1; d++) {
        lstm_diag_kernel<<<grid, THREADS, SMEM_TOTAL>>>(x, mask, b0, b1, b2, W0, d);
    }
    head_kernel<<<(Bsz * 32 + 255) / 256, 256>>>(Wd, bd, out);
}

// round 14
// speedup vs baseline: 1.3056x; 1.0285x over previous
#include <cuda_runtime.h>
#include <cuda_bf16.h>
#include <cstdint>

#define Bsz 2048
#define Tt  100
#define Uu  512
#define Cc  10
#define G4  2048   // 4*U

#define BM      64       // compacted batch rows per CTA
#define THREADS 256      // 8 warps = 2 rowWarps x 4 colWarps
#define NS      2        // pipeline stages

#define A_BYTES 8192     // 64 rows x 128B (64 bf16 k)
#define B_BYTES 32768    // 256 cols x 128B
#define STAGE_BYTES (A_BYTES + B_BYTES)     // 40960
#define SMEM_TOTAL (NS * STAGE_BYTES + 1024)

// ---------------- device state ----------------
__device__ __nv_bfloat16 g_h[3][2][Bsz * Uu];                 // ping-pong h, PLAIN [b][512]
__device__ float         g_c[3][Bsz * Uu];                     // c fp32, linear
__device__ __align__(1024) __nv_bfloat16 g_w0[512  * G4];      // tiled+swizzled bf16 weights
__device__ __align__(1024) __nv_bfloat16 g_w1[1024 * G4];
__device__ __align__(1024) __nv_bfloat16 g_w2[1024 * G4];
__device__ int g_order[Tt][Bsz];                               // per-t: active rows, then inactive
__device__ int g_count[Tt];

// ---------------- helpers ----------------
__device__ __forceinline__ void mbar_init(uint32_t a, uint32_t cnt) {
    asm volatile("mbarrier.init.shared::cta.b64 [%0], %1;" ::"r"(a), "r"(cnt) : "memory");
}
__device__ __forceinline__ void mbar_expect_tx(uint32_t a, uint32_t bytes) {
    asm volatile("mbarrier.arrive.expect_tx.shared::cta.b64 _, [%0], %1;" ::"r"(a), "r"(bytes) : "memory");
}
__device__ __forceinline__ void mbar_wait(uint32_t a, uint32_t parity) {
    asm volatile(
        "{\n\t"
        ".reg .pred P;\n\t"
        "WL%=:\n\t"
        "mbarrier.try_wait.parity.acquire.cta.shared::cta.b64 P, [%0], %1, 0x989680;\n\t"
        "@P bra WD%=;\n\t"
        "bra WL%=;\n\t"
        "WD%=:\n\t"
        "}" ::"r"(a), "r"(parity) : "memory");
}
__device__ __forceinline__ void bulk_g2s(uint32_t dst, const void* src, uint32_t bytes, uint32_t mbar) {
    asm volatile(
        "cp.async.bulk.shared::cluster.global.mbarrier::complete_tx::bytes [%0], [%1], %2, [%3];"
        ::"r"(dst), "l"(src), "r"(bytes), "r"(mbar) : "memory");
}
__device__ __forceinline__ void cp16(uint32_t dst, const void* src) {
    asm volatile("cp.async.cg.shared.global [%0], [%1], 16;" ::"r"(dst), "l"(src));
}
__device__ __forceinline__ void mma_bf16(float* d, const unsigned* a, const unsigned* b) {
    asm volatile(
        "mma.sync.aligned.m16n8k16.row.col.f32.bf16.bf16.f32 "
        "{%0,%1,%2,%3}, {%4,%5,%6,%7}, {%8,%9}, {%0,%1,%2,%3};"
        : "+f"(d[0]), "+f"(d[1]), "+f"(d[2]), "+f"(d[3])
        : "r"(a[0]), "r"(a[1]), "r"(a[2]), "r"(a[3]), "r"(b[0]), "r"(b[1]));
}
__device__ __forceinline__ void ldsm_x4(unsigned& r0, unsigned& r1, unsigned& r2, unsigned& r3,
                                        uint32_t addr) {
    asm volatile("ldmatrix.sync.aligned.m8n8.x4.shared.b16 {%0,%1,%2,%3}, [%4];"
                 : "=r"(r0), "=r"(r1), "=r"(r2), "=r"(r3) : "r"(addr));
}
__device__ __forceinline__ float fsigmoid(float x) { return 1.0f / (1.0f + __expf(-x)); }
__device__ __forceinline__ float ftanh(float x)    { return 1.0f - 2.0f / (__expf(2.0f * x) + 1.0f); }

// ---------------- fused prep kernel ----------------
//  [0,256)      zero state
//  [256,512)    wprep layer0
//  [512,1024)   wprep layer1
//  [1024,1536)  wprep layer2
//  [1536,1636)  compact (t = bid-1536)
__device__ __forceinline__ void wprep_body(const float* W, const float* Uw, int layer,
                                           int bid, int nblk, int tid) {
    int K   = (layer == 0) ? 512 : 1024;
    int Klo = (layer == 0) ? 0 : 512;
    int nkt = K / 64;
    char* dst = (char*)((layer == 0) ? g_w0 : ((layer == 1) ? g_w1 : g_w2));
    int totalPairs = K * G4 / 2;
    for (int idx = bid * 256 + tid; idx < totalPairs; idx += nblk * 256) {
        int klp = idx & 31;
        int c   = (idx >> 5) & 255;
        int blk = idx >> 13;
        int kt  = blk % nkt;
        int nt  = blk / nkt;
        int z   = (c >> 6) * 512 + nt * 64 + (c & 63);
        int kg  = kt * 64 + klp * 2;
        float v0, v1;
        if (kg < Klo) { v0 = W[kg * G4 + z]; v1 = W[(kg + 1) * G4 + z]; }
        else          { v0 = Uw[(kg - Klo) * G4 + z]; v1 = Uw[(kg + 1 - Klo) * G4 + z]; }
        uint32_t off = (uint32_t)(nt * nkt + kt) * B_BYTES + c * 128 +
                       (((uint32_t)klp * 4) ^ (((uint32_t)c & 7) * 16));
        *(__nv_bfloat162*)(dst + off) = __floats2bfloat162_rn(v0, v1);
    }
}

__global__ void prep_kernel(const int* __restrict__ mask,
                            const float* __restrict__ W1, const float* __restrict__ U0,
                            const float* __restrict__ U1, const float* __restrict__ W2,
                            const float* __restrict__ U2)
{
    const int bid = blockIdx.x, tid = threadIdx.x;
    if (bid < 256) {
        int nh = 3 * 2 * Bsz * Uu;
        int nc = 3 * Bsz * Uu;
        __nv_bfloat16* h = &g_h[0][0][0];
        float* c = &g_c[0][0];
        for (int i = bid * 256 + tid; i < nh; i += 256 * 256)
            h[i] = __float2bfloat16(0.0f);
        for (int i = bid * 256 + tid; i < nc; i += 256 * 256)
            c[i] = 0.0f;
    } else if (bid < 512) {
        wprep_body((const float*)0, U0, 0, bid - 256, 256, tid);
    } else if (bid < 1024) {
        wprep_body(W1, U1, 1, bid - 512, 512, tid);
    } else if (bid < 1536) {
        wprep_body(W2, U2, 2, bid - 1024, 512, tid);
    } else {
        // compact: stable partition of rows by mask at t
        __shared__ int part[256];
        int t = bid - 1536;
        int ml[8], lc = 0;
#pragma unroll
        for (int j = 0; j < 8; j++) {
            int b = tid * 8 + j;
            ml[j] = (mask[b * Tt + t] != 0) ? 1 : 0;
            lc += ml[j];
        }
        part[tid] = lc;
        __syncthreads();
        for (int off = 1; off < 256; off <<= 1) {
            int v = (tid >= off) ? part[tid - off] : 0;
            __syncthreads();
            part[tid] += v;
            __syncthreads();
        }
        int incl  = part[tid];
        int base  = incl - lc;
        int total = part[255];
        int a = base, iv = tid * 8 - base;
#pragma unroll
        for (int j = 0; j < 8; j++) {
            int b = tid * 8 + j;
            if (ml[j]) g_order[t][a++]          = b;
            else       g_order[t][total + iv++] = b;
        }
        if (tid == 0) g_count[t] = total;
    }
}

// ---------------- fused LSTM diagonal step ----------------
// Diagonal d: layer = blockIdx.z processes t = d - layer (wavefront).
// Single-barrier pipeline: per k-tile, one __syncthreads that simultaneously
// (a) makes stage-s A data visible CTA-wide and (b) proves all warps finished
// reading stage s^1 in the previous iteration, after which stage s^1 is
// immediately refilled, overlapping with compute of stage s.
__global__ void __launch_bounds__(THREADS, 2)
lstm_diag_kernel(const float* __restrict__ x, const int* __restrict__ mask,
                 const float* __restrict__ b0, const float* __restrict__ b1,
                 const float* __restrict__ b2, const float* __restrict__ W0,
                 int d)
{
    const int layer = blockIdx.z;
    const int t = d - layer;
    if (t < 0 || t >= Tt) return;

    const int nkt = (layer == 0) ? 8 : 16;
    const char* wB = (const char*)((layer == 0) ? g_w0 : ((layer == 1) ? g_w1 : g_w2));
    const float* bias = (layer == 0) ? b0 : ((layer == 1) ? b1 : b2);
    const int p = t & 1;
    const char* hOwnOld = (const char*)g_h[layer][p];
    char*       hOwnNew = (char*)g_h[layer][p ^ 1];
    const char* hLow    = (layer == 0) ? hOwnOld : (const char*)g_h[layer - 1][p ^ 1];
    float*      Cst     = g_c[layer];

    extern __shared__ char smem[];
    __shared__ __align__(16) uint64_t barmem[NS];
    __shared__ int ords[BM];

    const uint32_t sdata = ((uint32_t)__cvta_generic_to_shared(smem) + 1023u) & ~1023u;
    const uint32_t barb  = (uint32_t)__cvta_generic_to_shared(barmem);

    const int tid  = threadIdx.x;
    const int lane = tid & 31, warp = tid >> 5;
    const int colWarp = warp & 3, rowWarp = warp >> 2;
    const int g = lane >> 2, tig = lane & 3;
    const int nt   = blockIdx.x;
    const int row0 = blockIdx.y * BM;
    const int u0   = nt * 64;
    const int count = g_count[t];

    if (row0 >= count && nt != 0) return;

    if (tid < BM) ords[tid] = g_order[t][row0 + tid];
    if (tid == 0) {
        for (int s = 0; s < NS; s++) mbar_init(barb + 8 * s, 1);
        asm volatile("fence.proxy.async.shared::cta;" ::: "memory");
    }
    __syncthreads();

    if (row0 >= count) {
        // pure copy CTA (nt==0): h_new = h_old for these inactive rows
        for (int idx = tid; idx < BM * 64; idx += THREADS) {
            int r  = idx >> 6, ck = idx & 63;
            size_t off = (size_t)ords[r] * 1024 + ck * 16;
            *(uint4*)(hOwnNew + off) = *(const uint4*)(hOwnOld + off);
        }
        return;
    }

    // ---- producers ----
    auto issueA = [&](int kt, int s) {
        const char* base = (kt < 8) ? (hLow + (size_t)kt * 128)
                                    : (hOwnOld + (size_t)(kt - 8) * 128);
#pragma unroll
        for (int i = 0; i < 2; i++) {
            int c  = i * THREADS + tid;
            int r  = c >> 3, ck = c & 7;
            uint32_t dst = sdata + s * STAGE_BYTES + r * 128 +
                           (((uint32_t)ck * 16) ^ (((uint32_t)r & 7) * 16));
            cp16(dst, base + (size_t)ords[r] * 1024 + ck * 16);
        }
        asm volatile("cp.async.commit_group;");
    };
    auto issueB = [&](int kt, int s) {
        uint32_t full = barb + 8 * s;
        mbar_expect_tx(full, B_BYTES);
        bulk_g2s(sdata + s * STAGE_BYTES + A_BYTES,
                 wB + (size_t)(nt * nkt + kt) * B_BYTES, B_BYTES, full);
    };

    // prologue: stage 0 only; stage 1 is issued inside iteration 0
    issueA(0, 0);
    if (tid == 0) issueB(0, 0);

    float acc[2][8][4];
#pragma unroll
    for (int m = 0; m < 2; m++)
#pragma unroll
        for (int j = 0; j < 8; j++)
#pragma unroll
            for (int r = 0; r < 4; r++) acc[m][j][r] = 0.0f;

    // ---- per-lane ldmatrix address constants ----
    const int ri = lane & 7, mi = lane >> 3;
    const uint32_t swzL  = (uint32_t)ri * 16;
    const uint32_t aHalf = (uint32_t)(mi >> 1) * 16;                 // A: k-half select
    const uint32_t aRow0 = (uint32_t)(rowWarp * 32 + (mi & 1) * 8 + ri) * 128;  // A m=0
    const uint32_t bHalf = (uint32_t)(mi & 1) * 16;                  // B: k-half select
    const uint32_t bCol  = (uint32_t)(colWarp * 16 + (mi >> 1) * 8 + ri) * 128 + A_BYTES;

    for (int kt = 0; kt < nkt; kt++) {
        int s = kt & 1;
        // exactly one A group in flight (issued last iteration or prologue)
        asm volatile("cp.async.wait_group 0;");
        mbar_wait(barb + 8 * s, (uint32_t)((kt >> 1) & 1));
        __syncthreads();   // A(s) visible CTA-wide + all warps done reading stage s^1

        // refill the vacated stage NOW, overlapping with compute below
        if (kt + 1 < nkt) {
            issueA(kt + 1, s ^ 1);
            if (tid == 0) issueB(kt + 1, s ^ 1);
        }

        const uint32_t sb = sdata + s * STAGE_BYTES;

#pragma unroll
        for (int kq = 0; kq < 4; kq++) {
            const uint32_t kB = (uint32_t)kq * 32;
            unsigned af[2][4];
            ldsm_x4(af[0][0], af[0][1], af[0][2], af[0][3],
                    sb + aRow0 + ((kB + aHalf) ^ swzL));
            ldsm_x4(af[1][0], af[1][1], af[1][2], af[1][3],
                    sb + aRow0 + 16 * 128 + ((kB + aHalf) ^ swzL));
            unsigned bf[8][2];
#pragma unroll
            for (int q = 0; q < 4; q++) {
                ldsm_x4(bf[2 * q][0], bf[2 * q][1], bf[2 * q + 1][0], bf[2 * q + 1][1],
                        sb + bCol + (uint32_t)q * 64 * 128 + ((kB + bHalf) ^ swzL));
            }
#pragma unroll
            for (int m = 0; m < 2; m++)
#pragma unroll
                for (int j = 0; j < 8; j++)
                    mma_bf16(acc[m][j], af[m], bf[j]);
        }
        // no trailing barrier: next iteration's sync (after its waits) orders reuse
    }

    // ---- fused epilogue ----
#pragma unroll
    for (int m = 0; m < 2; m++) {
#pragma unroll
        for (int rs = 0; rs < 2; rs++) {
            int ro = rowWarp * 32 + m * 16 + g + rs * 8;
            int bg = ords[ro];
            int mk = mask[bg * Tt + t];
            float xv = (layer == 0) ? x[bg * Tt + t] : 0.0f;
#pragma unroll
            for (int half = 0; half < 2; half++) {
                int u = u0 + colWarp * 16 + half * 8 + tig * 2;   // even
                size_t hoff = (size_t)bg * 1024 + (size_t)u * 2;
                __nv_bfloat162 hold2 = *(const __nv_bfloat162*)(hOwnOld + hoff);
                float2 c2 = *(const float2*)&Cst[bg * Uu + u];
                float cv[2] = {c2.x, c2.y}, hv[2];
#pragma unroll
                for (int pp = 0; pp < 2; pp++) {
                    int uu = u + pp;
                    int ri2 = rs * 2 + pp;
                    float zi = acc[m][0 + half][ri2] + bias[uu];
                    float zf = acc[m][2 + half][ri2] + bias[512 + uu];
                    float zg = acc[m][4 + half][ri2] + bias[1024 + uu];
                    float zo = acc[m][6 + half][ri2] + bias[1536 + uu];
                    if (layer == 0) {
                        zi += xv * W0[uu];
                        zf += xv * W0[512 + uu];
                        zg += xv * W0[1024 + uu];
                        zo += xv * W0[1536 + uu];
                    }
                    float co = cv[pp];
                    float ig = fsigmoid(zi);
                    float fg = fsigmoid(zf);
                    float gg = ftanh(zg);
                    float og = fsigmoid(zo);
                    float cn = fg * co + ig * gg;
                    float hn = og * ftanh(cn);
                    if (!mk) { cn = co; hn = __bfloat162float(pp ? hold2.y : hold2.x); }
                    cv[pp] = cn;
                    hv[pp] = hn;
                }
                *(float2*)&Cst[bg * Uu + u] = make_float2(cv[0], cv[1]);
                *(__nv_bfloat162*)(hOwnNew + hoff) = __floats2bfloat162_rn(hv[0], hv[1]);
            }
        }
    }
}

// ---------------- softmax head ----------------
__global__ void head_kernel(const float* __restrict__ Wd, const float* __restrict__ bd,
                            float* __restrict__ out)
{
    int gw   = (blockIdx.x * blockDim.x + threadIdx.x) >> 5;
    int lane = threadIdx.x & 31;
    if (gw >= Bsz) return;
    const __nv_bfloat16* h = g_h[2][0];   // layer2 @ t=99 writes buffer (99&1)^1 = 0
    float a[Cc];
#pragma unroll
    for (int c = 0; c < Cc; c++) a[c] = 0.0f;
    for (int k = lane; k < Uu; k += 32) {
        float hv = __bfloat162float(h[(size_t)gw * Uu + k]);
#pragma unroll
        for (int c = 0; c < Cc; c++) a[c] += hv * Wd[k * Cc + c];
    }
#pragma unroll
    for (int c = 0; c < Cc; c++)
#pragma unroll
        for (int off = 16; off > 0; off >>= 1)
            a[c] += __shfl_xor_sync(0xffffffffu, a[c], off);
    if (lane == 0) {
        float logit[Cc], mx = -1e30f;
#pragma unroll
        for (int c = 0; c < Cc; c++) { logit[c] = a[c] + bd[c]; mx = fmaxf(mx, logit[c]); }
        float s = 0.0f;
#pragma unroll
        for (int c = 0; c < Cc; c++) { logit[c] = expf(logit[c] - mx); s += logit[c]; }
        float inv = 1.0f / s;
#pragma unroll
        for (int c = 0; c < Cc; c++) out[gw * Cc + c] = logit[c] * inv;
    }
}

// ---------------- launch ----------------
extern "C" void kernel_launch(void* const* d_in, const int* in_sizes, int n_in,
                              void* d_out, int out_size)
{
    const float* x    = (const float*)d_in[0];
    const int*   mask = (const int*)  d_in[1];
    const float* W0   = (const float*)d_in[2];
    const float* U0   = (const float*)d_in[3];
    const float* b0   = (const float*)d_in[4];
    const float* W1   = (const float*)d_in[5];
    const float* U1   = (const float*)d_in[6];
    const float* b1   = (const float*)d_in[7];
    const float* W2   = (const float*)d_in[8];
    const float* U2   = (const float*)d_in[9];
    const float* b2   = (const float*)d_in[10];
    const float* Wd   = (const float*)d_in[11];
    const float* bd   = (const float*)d_in[12];
    float* out = (float*)d_out;

    cudaFuncSetAttribute(lstm_diag_kernel, cudaFuncAttributeMaxDynamicSharedMemorySize,
                         SMEM_TOTAL);

    prep_kernel<<<1636, 256>>>(mask, W1, U0, U1, W2, U2);

    dim3 grid(8, 32, 3);   // u-tiles x row-tiles x layers (wavefront diagonal)
    for (int d = 0; d <= Tt + 1; d++) {
        lstm_diag_kernel<<<grid, THREADS, SMEM_TOTAL>>>(x, mask, b0, b1, b2, W0, d);
    }
    head_kernel<<<(Bsz * 32 + 255) / 256, 256>>>(Wd, bd, out);
}